// round 5
// baseline (speedup 1.0000x reference)
#include <cuda_runtime.h>
#include <math.h>

#define VOCAB 50257
#define DIM   128
#define HID   128
#define GATES 512
#define BATCH 64
#define SEQ   2048

typedef unsigned long long ull;

// Projected embedding table: P[v][g] = dot(emb[v], W_ih[g]) + b_ih[g] + b_hh[g]
__device__ float g_P[(size_t)VOCAB * GATES];

#define FMA2(acc, a, b) \
    asm("fma.rn.f32x2 %0, %1, %2, %0;" : "+l"(acc) : "l"(a), "l"(b))

// ---------------------------------------------------------------------------
// Kernel 1: P = emb @ W_ih^T + b  (R1 scalar version — measured fastest)
// ---------------------------------------------------------------------------
__global__ __launch_bounds__(256) void proj_kernel(
    const float* __restrict__ emb,
    const float* __restrict__ W_ih,
    const float* __restrict__ b_ih,
    const float* __restrict__ b_hh)
{
    extern __shared__ float sm1[];
    float* As = sm1;              // [64][129]
    float* Bs = sm1 + 64 * 129;   // [64][129]

    const int tid  = threadIdx.x;
    const int tx   = tid & 15;
    const int ty   = tid >> 4;
    const int row0 = blockIdx.y << 6;
    const int n0   = blockIdx.x << 6;

    #pragma unroll
    for (int i = 0; i < 8; ++i) {
        int idx = tid + (i << 8);
        int m   = idx >> 5;
        int k4  = (idx & 31) << 2;
        int gm  = row0 + m;
        float4 a = make_float4(0.f, 0.f, 0.f, 0.f);
        if (gm < VOCAB)
            a = *reinterpret_cast<const float4*>(emb + (size_t)gm * DIM + k4);
        As[m * 129 + k4 + 0] = a.x;
        As[m * 129 + k4 + 1] = a.y;
        As[m * 129 + k4 + 2] = a.z;
        As[m * 129 + k4 + 3] = a.w;
        float4 w = *reinterpret_cast<const float4*>(W_ih + (size_t)(n0 + m) * DIM + k4);
        Bs[m * 129 + k4 + 0] = w.x;
        Bs[m * 129 + k4 + 1] = w.y;
        Bs[m * 129 + k4 + 2] = w.z;
        Bs[m * 129 + k4 + 3] = w.w;
    }
    __syncthreads();

    float acc[4][4];
    #pragma unroll
    for (int i = 0; i < 4; ++i)
        #pragma unroll
        for (int jj = 0; jj < 4; ++jj) acc[i][jj] = 0.f;

    const float* ap = As + (ty << 2) * 129;
    const float* bp = Bs + (tx << 2) * 129;

    #pragma unroll 8
    for (int k = 0; k < 128; ++k) {
        float a0 = ap[k], a1 = ap[k + 129], a2 = ap[k + 258], a3 = ap[k + 387];
        float b0 = bp[k], b1 = bp[k + 129], b2 = bp[k + 258], b3 = bp[k + 387];
        acc[0][0] += a0 * b0; acc[0][1] += a0 * b1; acc[0][2] += a0 * b2; acc[0][3] += a0 * b3;
        acc[1][0] += a1 * b0; acc[1][1] += a1 * b1; acc[1][2] += a1 * b2; acc[1][3] += a1 * b3;
        acc[2][0] += a2 * b0; acc[2][1] += a2 * b1; acc[2][2] += a2 * b2; acc[2][3] += a2 * b3;
        acc[3][0] += a3 * b0; acc[3][1] += a3 * b1; acc[3][2] += a3 * b2; acc[3][3] += a3 * b3;
    }

    int gn = n0 + (tx << 2);
    float bb0 = b_ih[gn + 0] + b_hh[gn + 0];
    float bb1 = b_ih[gn + 1] + b_hh[gn + 1];
    float bb2 = b_ih[gn + 2] + b_hh[gn + 2];
    float bb3 = b_ih[gn + 3] + b_hh[gn + 3];

    #pragma unroll
    for (int i = 0; i < 4; ++i) {
        int gm = row0 + (ty << 2) + i;
        if (gm < VOCAB) {
            float4 o = make_float4(acc[i][0] + bb0, acc[i][1] + bb1,
                                   acc[i][2] + bb2, acc[i][3] + bb3);
            *reinterpret_cast<float4*>(g_P + (size_t)gm * GATES + gn) = o;
        }
    }
}

// ---------------------------------------------------------------------------
// Kernel 2: recurrent LSTM, cluster-of-2 K-split, TWO interleaved batches
// per cluster. Weights shared across both recurrences (same wreg). b1's
// matvec/send issue fills b0's DSMEM round-trip; barriers amortized 2x.
// ---------------------------------------------------------------------------
__device__ __forceinline__ float sig_f(float x) {
    return __fdividef(1.f, 1.f + __expf(-x));
}
__device__ __forceinline__ float tanh_f(float x) {
    float e = __expf(fminf(-2.f * x, 30.f));
    return __fdividef(1.f - e, 1.f + e);
}
__device__ __forceinline__ unsigned cvta_smem(const void* p) {
    unsigned r;
    asm("{ .reg .u64 t; cvta.to.shared.u64 t, %1; cvt.u32.u64 %0, t; }"
        : "=r"(r) : "l"(p));
    return r;
}

#define MBWAIT(addr, par) do {                                                 \
    unsigned _done;                                                            \
    asm volatile(                                                              \
        "{\n\t.reg .pred p;\n\t"                                               \
        "mbarrier.try_wait.parity.acquire.cta.shared::cta.b64 p, [%1], %2;\n\t" \
        "selp.b32 %0, 1, 0, p;\n\t}"                                           \
        : "=r"(_done) : "r"(addr), "r"(par) : "memory");                       \
    if (!_done) {                                                              \
        asm volatile(                                                          \
            "{\n\t.reg .pred P1;\n\t"                                          \
            "WL_%=:\n\t"                                                       \
            "mbarrier.try_wait.parity.acquire.cta.shared::cta.b64 P1, [%0], %1, 0x989680;\n\t" \
            "@P1 bra.uni WD_%=;\n\t"                                           \
            "bra.uni WL_%=;\n\t"                                               \
            "WD_%=:\n\t}"                                                      \
            :: "r"(addr), "r"(par) : "memory");                                \
    }                                                                          \
} while (0)

// full 64-k matvec into PART (4 chains; weights in wreg, h broadcast LDS.128)
#define MATVEC(HS, PART) do {                                                  \
    ull _a0 = 0ull, _a1 = 0ull, _a2 = 0ull, _a3 = 0ull;                        \
    const ulonglong2* _hp = (const ulonglong2*)((HS) + (rank << 6));           \
    _Pragma("unroll")                                                          \
    for (int q = 0; q < 8; ++q) {                                              \
        ulonglong2 A = _hp[2 * q];                                             \
        ulonglong2 B = _hp[2 * q + 1];                                         \
        FMA2(_a0, wreg[4 * q + 0], A.x);                                       \
        FMA2(_a1, wreg[4 * q + 1], A.y);                                       \
        FMA2(_a2, wreg[4 * q + 2], B.x);                                       \
        FMA2(_a3, wreg[4 * q + 3], B.y);                                       \
    }                                                                          \
    float _s0, _s1, _s2, _s3, _s4, _s5, _s6, _s7;                              \
    asm("mov.b64 {%0,%1}, %2;" : "=f"(_s0), "=f"(_s1) : "l"(_a0));             \
    asm("mov.b64 {%0,%1}, %2;" : "=f"(_s2), "=f"(_s3) : "l"(_a1));             \
    asm("mov.b64 {%0,%1}, %2;" : "=f"(_s4), "=f"(_s5) : "l"(_a2));             \
    asm("mov.b64 {%0,%1}, %2;" : "=f"(_s6), "=f"(_s7) : "l"(_a3));             \
    (PART) = ((_s0 + _s1) + (_s2 + _s3)) + ((_s4 + _s5) + (_s6 + _s7));        \
} while (0)

#define SEND(PART, SLOT, BUF) do {                                             \
    unsigned _dst = rm_pbuf +                                                  \
        (unsigned)(((((SLOT) << 1) + (BUF)) * 512 + j) << 2);                  \
    asm volatile(                                                              \
        "st.async.shared::cluster.mbarrier::complete_tx::bytes.b32 [%0], %1, [%2];" \
        :: "r"(_dst), "r"(__float_as_uint(PART)),                              \
           "r"(rm_mbar + (unsigned)((SLOT) << 3)) : "memory");                 \
} while (0)

__global__ __launch_bounds__(512, 1) __cluster_dims__(2, 1, 1)
void lstm_kernel(
    const int*   __restrict__ tokens,
    const float* __restrict__ W_hh,
    float*       __restrict__ out)
{
    __shared__ __align__(16) ull   mbar[2];          // one per batch slot
    __shared__ __align__(16) float h_s[2][128];
    __shared__ __align__(16) float a_s[2][512];
    __shared__ __align__(16) float pbuf[2][2][512];  // [slot][buf][row]
    __shared__ int tok_s[2][SEQ];

    const int j    = threadIdx.x;
    const int cl   = blockIdx.x >> 1;      // cluster id: 2 batches
    const int rank = blockIdx.x & 1;
    const int peer = rank ^ 1;
    const int b0   = cl * 2;

    const ull* W64 = (const ull*)W_hh;
    ull wreg[32];                           // shared by both recurrences
    #pragma unroll
    for (int kk = 0; kk < 32; ++kk)
        wreg[kk] = W64[(size_t)j * 64 + (rank << 5) + kk];

    for (int idx = j; idx < 2 * SEQ; idx += 512)
        tok_s[idx >> 11][idx & (SEQ - 1)] =
            tokens[(size_t)b0 * SEQ + idx];

    if (j < 128) { h_s[0][j] = 0.f; h_s[1][j] = 0.f; }

    const unsigned mbar_a = cvta_smem(mbar);
    const unsigned pbuf_a = cvta_smem(pbuf);
    if (j == 0) {
        asm volatile("mbarrier.init.shared.b64 [%0], %1;" :: "r"(mbar_a),     "r"(1u) : "memory");
        asm volatile("mbarrier.init.shared.b64 [%0], %1;" :: "r"(mbar_a + 8), "r"(1u) : "memory");
    }
    __syncthreads();
    asm volatile("barrier.cluster.arrive.aligned;" ::: "memory");
    asm volatile("barrier.cluster.wait.aligned;"   ::: "memory");

    unsigned rm_mbar, rm_pbuf;
    asm("mapa.shared::cluster.u32 %0, %1, %2;" : "=r"(rm_mbar) : "r"(mbar_a), "r"(peer));
    asm("mapa.shared::cluster.u32 %0, %1, %2;" : "=r"(rm_pbuf) : "r"(pbuf_a), "r"(peer));

    const float* Pp = (const float*)g_P;
    const bool fold = ((j >> 8) == rank);   // each rank folds xg for half the rows
    float x0 = fold ? __ldg(Pp + (size_t)tok_s[0][0] * GATES + j) : 0.f;
    float x1 = fold ? __ldg(Pp + (size_t)tok_s[1][0] * GATES + j) : 0.f;
    float c0 = 0.f, c1 = 0.f;
    const bool sel_tanh = ((j >> 7) == 2);  // gate order i, f, g(tanh), o

    for (int t = 0; t < SEQ; ++t) {
        const int buf = t & 1;
        const unsigned par = (unsigned)(t & 1);
        if (j == 0) {   // arm both slots: 1 arrival + 2048 tx bytes each
            asm volatile("mbarrier.arrive.expect_tx.shared.b64 _, [%0], %1;"
                         :: "r"(mbar_a),     "r"(2048u) : "memory");
            asm volatile("mbarrier.arrive.expect_tx.shared.b64 _, [%0], %1;"
                         :: "r"(mbar_a + 8), "r"(2048u) : "memory");
        }

        // ---- batch 0: matvec + send ----
        float part0;
        MATVEC(h_s[0], part0);
        if (fold) part0 += x0;
        SEND(part0, 0, buf);
        if (fold && t + 1 < SEQ)
            x0 = __ldg(Pp + (size_t)tok_s[0][t + 1] * GATES + j);

        // ---- batch 1: matvec + send (fills batch 0's DSMEM transit) ----
        float part1;
        MATVEC(h_s[1], part1);
        if (fold) part1 += x1;
        SEND(part1, 1, buf);
        if (fold && t + 1 < SEQ)
            x1 = __ldg(Pp + (size_t)tok_s[1][t + 1] * GATES + j);

        // ---- batch 0: wait + activation ----
        MBWAIT(mbar_a, par);
        {
            float g0 = part0 + pbuf[0][buf][j];
            a_s[0][j] = sel_tanh ? tanh_f(g0) : sig_f(g0);
        }
        // ---- batch 1: wait + activation ----
        MBWAIT(mbar_a + 8, par);
        {
            float g1 = part1 + pbuf[1][buf][j];
            a_s[1][j] = sel_tanh ? tanh_f(g1) : sig_f(g1);
        }
        __syncthreads();      // publish all activations (both batches)

        if (j < 128) {        // redundant tails on both ranks, both batches
            float ai0 = a_s[0][j],       af0 = a_s[0][128 + j];
            float ag0 = a_s[0][256 + j], ao0 = a_s[0][384 + j];
            c0 = fmaf(af0, c0, ai0 * ag0);
            h_s[0][j] = ao0 * tanh_f(c0);

            float ai1 = a_s[1][j],       af1 = a_s[1][128 + j];
            float ag1 = a_s[1][256 + j], ao1 = a_s[1][384 + j];
            c1 = fmaf(af1, c1, ai1 * ag1);
            h_s[1][j] = ao1 * tanh_f(c1);
        }
        __syncthreads();      // publish h for next step (both batches)
    }

    if (rank == 0 && j < 128) {
        out[(size_t)(b0 + 0) * HID + j] = h_s[0][j];
        out[(size_t)(b0 + 1) * HID + j] = h_s[1][j];
        out[(size_t)BATCH * HID + (size_t)(b0 + 0) * HID + j] = c0;
        out[(size_t)BATCH * HID + (size_t)(b0 + 1) * HID + j] = c1;
    }

    asm volatile("barrier.cluster.arrive.aligned;" ::: "memory");
    asm volatile("barrier.cluster.wait.aligned;"   ::: "memory");
}

// ---------------------------------------------------------------------------
extern "C" void kernel_launch(void* const* d_in, const int* in_sizes, int n_in,
                              void* d_out, int out_size)
{
    const int*   tokens = (const int*)  d_in[0];
    const float* emb    = (const float*)d_in[1];
    const float* W_ih   = (const float*)d_in[2];
    const float* W_hh   = (const float*)d_in[3];
    const float* b_ih   = (const float*)d_in[4];
    const float* b_hh   = (const float*)d_in[5];
    float* out = (float*)d_out;

    const int smem1 = 2 * 64 * 129 * (int)sizeof(float);   // 66048 B
    cudaFuncSetAttribute(proj_kernel, cudaFuncAttributeMaxDynamicSharedMemorySize, smem1);

    dim3 g1(GATES / 64, (VOCAB + 63) / 64);
    proj_kernel<<<g1, 256, smem1>>>(emb, W_ih, b_ih, b_hh);
    lstm_kernel<<<BATCH, 512>>>(tokens, W_hh, out);   // 32 clusters x 2 CTAs
}

// round 6
// speedup vs baseline: 1.1660x; 1.1660x over previous
#include <cuda_runtime.h>
#include <math.h>

#define VOCAB 50257
#define DIM   128
#define HID   128
#define GATES 512
#define BATCH 64
#define SEQ   2048

typedef unsigned long long ull;

// Projected embedding table: P[v][g] = dot(emb[v], W_ih[g]) + b_ih[g] + b_hh[g]
__device__ float g_P[(size_t)VOCAB * GATES];

#define FMA2(acc, a, b) \
    asm("fma.rn.f32x2 %0, %1, %2, %0;" : "+l"(acc) : "l"(a), "l"(b))

// ---------------------------------------------------------------------------
// Kernel 1: P = emb @ W_ih^T + b  (R1 scalar version — measured fastest)
// ---------------------------------------------------------------------------
__global__ __launch_bounds__(256) void proj_kernel(
    const float* __restrict__ emb,
    const float* __restrict__ W_ih,
    const float* __restrict__ b_ih,
    const float* __restrict__ b_hh)
{
    extern __shared__ float sm1[];
    float* As = sm1;              // [64][129]
    float* Bs = sm1 + 64 * 129;   // [64][129]

    const int tid  = threadIdx.x;
    const int tx   = tid & 15;
    const int ty   = tid >> 4;
    const int row0 = blockIdx.y << 6;
    const int n0   = blockIdx.x << 6;

    #pragma unroll
    for (int i = 0; i < 8; ++i) {
        int idx = tid + (i << 8);
        int m   = idx >> 5;
        int k4  = (idx & 31) << 2;
        int gm  = row0 + m;
        float4 a = make_float4(0.f, 0.f, 0.f, 0.f);
        if (gm < VOCAB)
            a = *reinterpret_cast<const float4*>(emb + (size_t)gm * DIM + k4);
        As[m * 129 + k4 + 0] = a.x;
        As[m * 129 + k4 + 1] = a.y;
        As[m * 129 + k4 + 2] = a.z;
        As[m * 129 + k4 + 3] = a.w;
        float4 w = *reinterpret_cast<const float4*>(W_ih + (size_t)(n0 + m) * DIM + k4);
        Bs[m * 129 + k4 + 0] = w.x;
        Bs[m * 129 + k4 + 1] = w.y;
        Bs[m * 129 + k4 + 2] = w.z;
        Bs[m * 129 + k4 + 3] = w.w;
    }
    __syncthreads();

    float acc[4][4];
    #pragma unroll
    for (int i = 0; i < 4; ++i)
        #pragma unroll
        for (int jj = 0; jj < 4; ++jj) acc[i][jj] = 0.f;

    const float* ap = As + (ty << 2) * 129;
    const float* bp = Bs + (tx << 2) * 129;

    #pragma unroll 8
    for (int k = 0; k < 128; ++k) {
        float a0 = ap[k], a1 = ap[k + 129], a2 = ap[k + 258], a3 = ap[k + 387];
        float b0 = bp[k], b1 = bp[k + 129], b2 = bp[k + 258], b3 = bp[k + 387];
        acc[0][0] += a0 * b0; acc[0][1] += a0 * b1; acc[0][2] += a0 * b2; acc[0][3] += a0 * b3;
        acc[1][0] += a1 * b0; acc[1][1] += a1 * b1; acc[1][2] += a1 * b2; acc[1][3] += a1 * b3;
        acc[2][0] += a2 * b0; acc[2][1] += a2 * b1; acc[2][2] += a2 * b2; acc[2][3] += a2 * b3;
        acc[3][0] += a3 * b0; acc[3][1] += a3 * b1; acc[3][2] += a3 * b2; acc[3][3] += a3 * b3;
    }

    int gn = n0 + (tx << 2);
    float bb0 = b_ih[gn + 0] + b_hh[gn + 0];
    float bb1 = b_ih[gn + 1] + b_hh[gn + 1];
    float bb2 = b_ih[gn + 2] + b_hh[gn + 2];
    float bb3 = b_ih[gn + 3] + b_hh[gn + 3];

    #pragma unroll
    for (int i = 0; i < 4; ++i) {
        int gm = row0 + (ty << 2) + i;
        if (gm < VOCAB) {
            float4 o = make_float4(acc[i][0] + bb0, acc[i][1] + bb1,
                                   acc[i][2] + bb2, acc[i][3] + bb3);
            *reinterpret_cast<float4*>(g_P + (size_t)gm * GATES + gn) = o;
        }
    }
}

// ---------------------------------------------------------------------------
// Kernel 2: recurrent LSTM, cluster-of-2 K-split, shuffle tail.
//   Thread j owns gate row row(j) = (j&3)*128 + (j>>5)*8 + ((j>>2)&7), so the
//   4 gates of a unit live in 4 adjacent lanes of one warp. Tail = 2 serial
//   shfl_xor + redundant c per lane quad; ONE __syncthreads per step;
//   h_s double-buffered. Rank r holds W_hh[row][64r..64r+63] in registers.
// ---------------------------------------------------------------------------
__device__ __forceinline__ float sig_f(float x) {
    return __fdividef(1.f, 1.f + __expf(-x));
}
__device__ __forceinline__ float tanh_f(float x) {
    float e = __expf(fminf(-2.f * x, 30.f));
    return __fdividef(1.f - e, 1.f + e);
}
__device__ __forceinline__ unsigned cvta_smem(const void* p) {
    unsigned r;
    asm("{ .reg .u64 t; cvta.to.shared.u64 t, %1; cvt.u32.u64 %0, t; }"
        : "=r"(r) : "l"(p));
    return r;
}

#define MBWAIT(addr, par) do {                                                 \
    unsigned _done;                                                            \
    asm volatile(                                                              \
        "{\n\t.reg .pred p;\n\t"                                               \
        "mbarrier.try_wait.parity.acquire.cta.shared::cta.b64 p, [%1], %2;\n\t" \
        "selp.b32 %0, 1, 0, p;\n\t}"                                           \
        : "=r"(_done) : "r"(addr), "r"(par) : "memory");                       \
    if (!_done) {                                                              \
        asm volatile(                                                          \
            "{\n\t.reg .pred P1;\n\t"                                          \
            "WL_%=:\n\t"                                                       \
            "mbarrier.try_wait.parity.acquire.cta.shared::cta.b64 P1, [%0], %1, 0x989680;\n\t" \
            "@P1 bra.uni WD_%=;\n\t"                                           \
            "bra.uni WL_%=;\n\t"                                               \
            "WD_%=:\n\t}"                                                      \
            :: "r"(addr), "r"(par) : "memory");                                \
    }                                                                          \
} while (0)

__global__ __launch_bounds__(512, 1) __cluster_dims__(2, 1, 1)
void lstm_kernel(
    const int*   __restrict__ tokens,
    const float* __restrict__ W_hh,
    float*       __restrict__ out)
{
    __shared__ __align__(16) ull   mbar[1];
    __shared__ __align__(16) float h_s[2][128];      // double buffered
    __shared__ __align__(16) float pbuf[2][512];     // peer partials
    __shared__ int tok_s[SEQ];

    const int j    = threadIdx.x;
    const int b    = blockIdx.x >> 1;
    const int rank = blockIdx.x & 1;
    const int peer = rank ^ 1;
    const int g    = j & 3;                          // gate of this lane
    const int u    = ((j >> 5) << 3) + ((j >> 2) & 7);   // unit 0..127
    const int row  = (g << 7) + u;                   // gate row in [0,512)

    const ull* W64 = (const ull*)W_hh;
    ull wreg[32];
    #pragma unroll
    for (int kk = 0; kk < 32; ++kk)
        wreg[kk] = W64[(size_t)row * 64 + (rank << 5) + kk];

    for (int idx = j; idx < SEQ; idx += 512)
        tok_s[idx] = tokens[(size_t)b * SEQ + idx];

    if (j < 128) { h_s[0][j] = 0.f; h_s[1][j] = 0.f; }

    const unsigned mbar_a = cvta_smem(mbar);
    const unsigned pbuf_a = cvta_smem(pbuf);
    if (j == 0) {
        asm volatile("mbarrier.init.shared.b64 [%0], %1;"
                     :: "r"(mbar_a), "r"(1u) : "memory");
    }
    __syncthreads();
    asm volatile("barrier.cluster.arrive.aligned;" ::: "memory");
    asm volatile("barrier.cluster.wait.aligned;"   ::: "memory");

    unsigned rm_mbar, rm_pbuf;
    asm("mapa.shared::cluster.u32 %0, %1, %2;" : "=r"(rm_mbar) : "r"(mbar_a), "r"(peer));
    asm("mapa.shared::cluster.u32 %0, %1, %2;" : "=r"(rm_pbuf) : "r"(pbuf_a), "r"(peer));

    const float* Pp = (const float*)g_P;
    const bool fold = ((j >> 8) == rank);    // each rank folds xg for half the rows
    float x_cur = fold ? __ldg(Pp + (size_t)tok_s[0] * GATES + row) : 0.f;
    float c = 0.f, h_last = 0.f;
    const bool sel_tanh = (g == 2);          // gate order i, f, g(tanh), o

    for (int t = 0; t < SEQ; ++t) {
        const int buf = t & 1;
        if (j == 0) {   // arm phase: 1 arrival + 2048 tx bytes (512 x 4B)
            asm volatile("mbarrier.arrive.expect_tx.shared.b64 _, [%0], %1;"
                         :: "r"(mbar_a), "r"(2048u) : "memory");
        }

        float xg = x_cur;
        if (fold && t + 1 < SEQ)
            x_cur = __ldg(Pp + (size_t)tok_s[t + 1] * GATES + row);

        // 64-k matvec (4 chains, weights in regs, h broadcast LDS.128)
        ull a0 = 0ull, a1 = 0ull, a2 = 0ull, a3 = 0ull;
        {
            const ulonglong2* hp = (const ulonglong2*)(&h_s[buf][rank << 6]);
            #pragma unroll
            for (int q = 0; q < 8; ++q) {
                ulonglong2 A = hp[2 * q];
                ulonglong2 B = hp[2 * q + 1];
                FMA2(a0, wreg[4 * q + 0], A.x);
                FMA2(a1, wreg[4 * q + 1], A.y);
                FMA2(a2, wreg[4 * q + 2], B.x);
                FMA2(a3, wreg[4 * q + 3], B.y);
            }
        }
        float part;
        {
            float s0, s1, s2, s3, s4, s5, s6, s7;
            asm("mov.b64 {%0,%1}, %2;" : "=f"(s0), "=f"(s1) : "l"(a0));
            asm("mov.b64 {%0,%1}, %2;" : "=f"(s2), "=f"(s3) : "l"(a1));
            asm("mov.b64 {%0,%1}, %2;" : "=f"(s4), "=f"(s5) : "l"(a2));
            asm("mov.b64 {%0,%1}, %2;" : "=f"(s6), "=f"(s7) : "l"(a3));
            part = ((s0 + s1) + (s2 + s3)) + ((s4 + s5) + (s6 + s7));
        }
        if (fold) part += xg;

        {   // ship my partial to peer's pbuf[buf][j]
            unsigned dst = rm_pbuf + (unsigned)(((buf << 9) + j) << 2);
            asm volatile(
                "st.async.shared::cluster.mbarrier::complete_tx::bytes.b32 [%0], %1, [%2];"
                :: "r"(dst), "r"(__float_as_uint(part)), "r"(rm_mbar) : "memory");
        }

        MBWAIT(mbar_a, (unsigned)(t & 1));
        float gsum = part + pbuf[buf][j];
        float act = sel_tanh ? tanh_f(gsum) : sig_f(gsum);

        // gather i,f,g,o within the lane quad (2 serial shuffles)
        float x1 = __shfl_xor_sync(0xFFFFFFFFu, act, 1);
        float x2 = __shfl_xor_sync(0xFFFFFFFFu, act, 2);
        float x3 = __shfl_xor_sync(0xFFFFFFFFu, x1, 2);
        float ai  = (g == 0) ? act : (g == 1) ? x1 : (g == 2) ? x2 : x3;
        float af  = (g == 1) ? act : (g == 0) ? x1 : (g == 3) ? x2 : x3;
        float agv = (g == 2) ? act : (g == 3) ? x1 : (g == 0) ? x2 : x3;
        float ao  = (g == 3) ? act : (g == 2) ? x1 : (g == 1) ? x2 : x3;

        c = fmaf(af, c, ai * agv);           // redundant copy in all 4 lanes
        if (g == 0) {                        // owner lane computes + publishes h
            h_last = ao * tanh_f(c);
            h_s[buf ^ 1][u] = h_last;
        }
        __syncthreads();                     // single barrier per step
    }

    if (rank == 0 && g == 0) {
        out[(size_t)b * HID + u] = h_last;                        // h [1,64,128]
        out[(size_t)BATCH * HID + (size_t)b * HID + u] = c;       // c [1,64,128]
    }

    asm volatile("barrier.cluster.arrive.aligned;" ::: "memory");
    asm volatile("barrier.cluster.wait.aligned;"   ::: "memory");
}

// ---------------------------------------------------------------------------
extern "C" void kernel_launch(void* const* d_in, const int* in_sizes, int n_in,
                              void* d_out, int out_size)
{
    const int*   tokens = (const int*)  d_in[0];
    const float* emb    = (const float*)d_in[1];
    const float* W_ih   = (const float*)d_in[2];
    const float* W_hh   = (const float*)d_in[3];
    const float* b_ih   = (const float*)d_in[4];
    const float* b_hh   = (const float*)d_in[5];
    float* out = (float*)d_out;

    const int smem1 = 2 * 64 * 129 * (int)sizeof(float);   // 66048 B
    cudaFuncSetAttribute(proj_kernel, cudaFuncAttributeMaxDynamicSharedMemorySize, smem1);

    dim3 g1(GATES / 64, (VOCAB + 63) / 64);
    proj_kernel<<<g1, 256, smem1>>>(emb, W_ih, b_ih, b_hh);
    lstm_kernel<<<BATCH * 2, 512>>>(tokens, W_hh, out);
}

// round 8
// speedup vs baseline: 1.4716x; 1.2621x over previous
#include <cuda_runtime.h>
#include <cuda_bf16.h>
#include <math.h>

#define VOCAB 50257
#define DIM   128
#define HID   128
#define GATES 512
#define BATCH 64
#define SEQ   2048

typedef unsigned long long ull;

// Projected embedding table: P[v][g] = dot(emb[v], W_ih[g]) + b_ih[g] + b_hh[g]
__device__ float g_P[(size_t)VOCAB * GATES];

#define FMA2(acc, a, b) \
    asm("fma.rn.f32x2 %0, %1, %2, %0;" : "+l"(acc) : "l"(a), "l"(b))

// ===========================================================================
// Kernel 1: P = emb @ W_ih^T + b via mma.sync (HMMA) bf16 3-term split.
//   CTA: 256 thr / 8 warps, tile M=64 x N=64 x K=128; warp = m16 x n32.
//   SMEM tiles bf16 [64][136] (272 B row stride -> conflict-free ldmatrix).
// ===========================================================================
#define PROW 136          // bf16 per smem row (272 B)
#define OFF_AHI 0
#define OFF_ALO (OFF_AHI + 64 * PROW * 2)
#define OFF_BHI (OFF_ALO + 64 * PROW * 2)
#define OFF_BLO (OFF_BHI + 64 * PROW * 2)
#define OFF_BIAS (OFF_BLO + 64 * PROW * 2)
#define SM_PROJ (OFF_BIAS + 64 * 4)

__device__ __forceinline__ unsigned cvta_smem_u32(const void* p) {
    unsigned r;
    asm("{ .reg .u64 t; cvta.to.shared.u64 t, %1; cvt.u32.u64 %0, t; }"
        : "=r"(r) : "l"(p));
    return r;
}
__device__ __forceinline__ unsigned pack_hi(float a, float b) {
    __nv_bfloat162 v = __float22bfloat162_rn(make_float2(a, b));
    return *reinterpret_cast<unsigned*>(&v);
}

#define LDSM4(R0, R1, R2, R3, ADDR)                                         \
    asm volatile("ldmatrix.sync.aligned.m8n8.x4.shared.b16 "                \
                 "{%0,%1,%2,%3}, [%4];"                                     \
                 : "=r"(R0), "=r"(R1), "=r"(R2), "=r"(R3) : "r"(ADDR))

#define MMA16816(D, A0, A1, A2, A3, B0, B1)                                 \
    asm volatile("mma.sync.aligned.m16n8k16.row.col.f32.bf16.bf16.f32 "     \
                 "{%0,%1,%2,%3}, {%4,%5,%6,%7}, {%8,%9}, {%0,%1,%2,%3};"    \
                 : "+f"((D)[0]), "+f"((D)[1]), "+f"((D)[2]), "+f"((D)[3])   \
                 : "r"(A0), "r"(A1), "r"(A2), "r"(A3), "r"(B0), "r"(B1))

__global__ __launch_bounds__(256) void proj_mma_kernel(
    const float* __restrict__ emb,
    const float* __restrict__ W_ih,
    const float* __restrict__ b_ih,
    const float* __restrict__ b_hh)
{
    extern __shared__ __align__(16) unsigned char sm[];
    const unsigned base = cvta_smem_u32(sm);

    const int tid  = threadIdx.x;
    const int m0   = blockIdx.x << 6;
    const int n0   = blockIdx.y << 6;

    // ---- load + hi/lo split: thread t -> row t>>2, cols 32*(t&3)..+31 ----
    {
        const int r  = tid >> 2;
        const int c0 = (tid & 3) << 5;
        const int gm = m0 + r;
        const bool av = (gm < VOCAB);
        const float4* arow = (const float4*)(emb + (size_t)(av ? gm : 0) * DIM + c0);
        const float4* brow = (const float4*)(W_ih + (size_t)(n0 + r) * DIM + c0);
        unsigned char* Ahi = sm + OFF_AHI + r * (PROW * 2) + c0 * 2;
        unsigned char* Alo = sm + OFF_ALO + r * (PROW * 2) + c0 * 2;
        unsigned char* Bhi = sm + OFF_BHI + r * (PROW * 2) + c0 * 2;
        unsigned char* Blo = sm + OFF_BLO + r * (PROW * 2) + c0 * 2;

        #pragma unroll
        for (int i = 0; i < 8; ++i) {
            float4 va = av ? arow[i] : make_float4(0.f, 0.f, 0.f, 0.f);
            float4 vb = brow[i];
            // hi = bf16(v), lo = bf16(v - hi)
            unsigned ah0 = pack_hi(va.x, va.y), ah1 = pack_hi(va.z, va.w);
            unsigned bh0 = pack_hi(vb.x, vb.y), bh1 = pack_hi(vb.z, vb.w);
            __nv_bfloat162 ah0b = *reinterpret_cast<__nv_bfloat162*>(&ah0);
            __nv_bfloat162 ah1b = *reinterpret_cast<__nv_bfloat162*>(&ah1);
            __nv_bfloat162 bh0b = *reinterpret_cast<__nv_bfloat162*>(&bh0);
            __nv_bfloat162 bh1b = *reinterpret_cast<__nv_bfloat162*>(&bh1);
            unsigned al0 = pack_hi(va.x - __bfloat162float(ah0b.x),
                                   va.y - __bfloat162float(ah0b.y));
            unsigned al1 = pack_hi(va.z - __bfloat162float(ah1b.x),
                                   va.w - __bfloat162float(ah1b.y));
            unsigned bl0 = pack_hi(vb.x - __bfloat162float(bh0b.x),
                                   vb.y - __bfloat162float(bh0b.y));
            unsigned bl1 = pack_hi(vb.z - __bfloat162float(bh1b.x),
                                   vb.w - __bfloat162float(bh1b.y));
            *(uint2*)(Ahi + i * 8) = make_uint2(ah0, ah1);
            *(uint2*)(Alo + i * 8) = make_uint2(al0, al1);
            *(uint2*)(Bhi + i * 8) = make_uint2(bh0, bh1);
            *(uint2*)(Blo + i * 8) = make_uint2(bl0, bl1);
        }
        if (tid < 64)
            ((float*)(sm + OFF_BIAS))[tid] = b_ih[n0 + tid] + b_hh[n0 + tid];
    }
    __syncthreads();

    // ---- mma: warp w -> m strip (w&3)*16, n strip (w>>2)*32 ----
    const int w    = tid >> 5;
    const int lane = tid & 31;
    const int ms   = (w & 3) << 4;
    const int ns   = (w >> 2) << 5;

    float acc[4][4];
    #pragma unroll
    for (int nt = 0; nt < 4; ++nt)
        #pragma unroll
        for (int i = 0; i < 4; ++i) acc[nt][i] = 0.f;

    // ldmatrix lane addressing (row within tile group)
    const int a_row = ms + (lane & 15);
    const int a_k8  = (lane & 16) ? 16 : 0;           // bytes: 8 bf16 = 16 B
    const int b_row = ns + (lane & 7) + ((lane & 16) ? 8 : 0);
    const int b_k8  = (lane & 8) ? 16 : 0;

    const unsigned Ahi_a = base + OFF_AHI + a_row * (PROW * 2) + a_k8;
    const unsigned Alo_a = base + OFF_ALO + a_row * (PROW * 2) + a_k8;
    const unsigned Bhi0  = base + OFF_BHI + b_row * (PROW * 2) + b_k8;
    const unsigned Bhi1  = Bhi0 + 16 * (PROW * 2);
    const unsigned Blo0  = base + OFF_BLO + b_row * (PROW * 2) + b_k8;
    const unsigned Blo1  = Blo0 + 16 * (PROW * 2);

    #pragma unroll
    for (int s = 0; s < 8; ++s) {
        const unsigned ko = s * 32;    // 16 bf16 = 32 B per kstep
        unsigned ah0, ah1, ah2, ah3, al0, al1, al2, al3;
        LDSM4(ah0, ah1, ah2, ah3, Ahi_a + ko);
        LDSM4(al0, al1, al2, al3, Alo_a + ko);
        unsigned bh[8], bl[8];
        LDSM4(bh[0], bh[1], bh[2], bh[3], Bhi0 + ko);
        LDSM4(bh[4], bh[5], bh[6], bh[7], Bhi1 + ko);
        LDSM4(bl[0], bl[1], bl[2], bl[3], Blo0 + ko);
        LDSM4(bl[4], bl[5], bl[6], bl[7], Blo1 + ko);
        #pragma unroll
        for (int nt = 0; nt < 4; ++nt) {
            MMA16816(acc[nt], ah0, ah1, ah2, ah3, bh[2 * nt], bh[2 * nt + 1]);
            MMA16816(acc[nt], ah0, ah1, ah2, ah3, bl[2 * nt], bl[2 * nt + 1]);
            MMA16816(acc[nt], al0, al1, al2, al3, bh[2 * nt], bh[2 * nt + 1]);
        }
    }

    // ---- epilogue: d0,d1 -> row l/4; d2,d3 -> row l/4+8; cols (l%4)*2,+1 ----
    {
        const float* bias = (const float*)(sm + OFF_BIAS);
        const int row0 = m0 + ms + (lane >> 2);
        const int row1 = row0 + 8;
        const int cloc = ns + ((lane & 3) << 1);
        #pragma unroll
        for (int nt = 0; nt < 4; ++nt) {
            const int cl = cloc + nt * 8;
            const float b0 = bias[cl], b1 = bias[cl + 1];
            if (row0 < VOCAB)
                *(float2*)(g_P + (size_t)row0 * GATES + n0 + cl) =
                    make_float2(acc[nt][0] + b0, acc[nt][1] + b1);
            if (row1 < VOCAB)
                *(float2*)(g_P + (size_t)row1 * GATES + n0 + cl) =
                    make_float2(acc[nt][2] + b0, acc[nt][3] + b1);
        }
    }
}

// ===========================================================================
// Kernel 2: recurrent LSTM — R2 version verbatim (measured 1293 us).
// ===========================================================================
__device__ __forceinline__ float sig_f(float x) {
    return __fdividef(1.f, 1.f + __expf(-x));
}
__device__ __forceinline__ float tanh_f(float x) {
    float e = __expf(fminf(-2.f * x, 30.f));
    return __fdividef(1.f - e, 1.f + e);
}
__device__ __forceinline__ unsigned cvta_smem(const void* p) {
    unsigned r;
    asm("{ .reg .u64 t; cvta.to.shared.u64 t, %1; cvt.u32.u64 %0, t; }"
        : "=r"(r) : "l"(p));
    return r;
}

#define MBWAIT(addr, par) do {                                                 \
    unsigned _done;                                                            \
    asm volatile(                                                              \
        "{\n\t.reg .pred p;\n\t"                                               \
        "mbarrier.try_wait.parity.acquire.cta.shared::cta.b64 p, [%1], %2;\n\t" \
        "selp.b32 %0, 1, 0, p;\n\t}"                                           \
        : "=r"(_done) : "r"(addr), "r"(par) : "memory");                       \
    if (!_done) {                                                              \
        asm volatile(                                                          \
            "{\n\t.reg .pred P1;\n\t"                                          \
            "WL_%=:\n\t"                                                       \
            "mbarrier.try_wait.parity.acquire.cta.shared::cta.b64 P1, [%0], %1, 0x989680;\n\t" \
            "@P1 bra.uni WD_%=;\n\t"                                           \
            "bra.uni WL_%=;\n\t"                                               \
            "WD_%=:\n\t}"                                                      \
            :: "r"(addr), "r"(par) : "memory");                                \
    }                                                                          \
} while (0)

__global__ __launch_bounds__(512, 1) __cluster_dims__(2, 1, 1)
void lstm_kernel(
    const int*   __restrict__ tokens,
    const float* __restrict__ W_hh,
    float*       __restrict__ out)
{
    __shared__ __align__(16) ull   mbar[1];
    __shared__ __align__(16) float h_s[128];
    __shared__ __align__(16) float a_s[512];
    __shared__ __align__(16) float pbuf[2][512];   // peer partials, double buffered
    __shared__ int tok_s[SEQ];

    const int j    = threadIdx.x;
    const int b    = blockIdx.x >> 1;
    const int rank = blockIdx.x & 1;
    const int peer = rank ^ 1;

    const ull* W64 = (const ull*)W_hh;

    ull wreg[32];
    #pragma unroll
    for (int kk = 0; kk < 32; ++kk)
        wreg[kk] = W64[(size_t)j * 64 + (rank << 5) + kk];

    if (rank == 0) {
        for (int idx = j; idx < SEQ; idx += 512)
            tok_s[idx] = tokens[(size_t)b * SEQ + idx];
    }
    if (j < 128) h_s[j] = 0.f;

    const unsigned mbar_a = cvta_smem(mbar);
    const unsigned pbuf_a = cvta_smem(pbuf);
    if (j == 0) {
        asm volatile("mbarrier.init.shared.b64 [%0], %1;"
                     :: "r"(mbar_a), "r"(1u) : "memory");
    }
    __syncthreads();
    asm volatile("barrier.cluster.arrive.aligned;" ::: "memory");
    asm volatile("barrier.cluster.wait.aligned;"   ::: "memory");

    unsigned rm_mbar, rm_pbuf;
    asm("mapa.shared::cluster.u32 %0, %1, %2;" : "=r"(rm_mbar) : "r"(mbar_a), "r"(peer));
    asm("mapa.shared::cluster.u32 %0, %1, %2;" : "=r"(rm_pbuf) : "r"(pbuf_a), "r"(peer));

    const float* Pp = (const float*)g_P;
    float x_cur = (rank == 0) ? __ldg(Pp + (size_t)tok_s[0] * GATES + j) : 0.f;
    float c = 0.f;
    const bool sel_tanh = ((j >> 7) == 2);   // gate order i, f, g(tanh), o
    const ulonglong2* h2 = (const ulonglong2*)(h_s + (rank << 6));

    for (int t = 0; t < SEQ; ++t) {
        if (j == 0) {
            asm volatile("mbarrier.arrive.expect_tx.shared.b64 _, [%0], %1;"
                         :: "r"(mbar_a), "r"(2048u) : "memory");
        }

        float xg = x_cur;
        if (rank == 0 && t + 1 < SEQ)
            x_cur = __ldg(Pp + (size_t)tok_s[t + 1] * GATES + j);

        ull a0 = 0ull, a1 = 0ull, a2 = 0ull, a3 = 0ull;
        #pragma unroll
        for (int q = 0; q < 8; ++q) {
            ulonglong2 ha = h2[2 * q];
            ulonglong2 hb = h2[2 * q + 1];
            FMA2(a0, wreg[4 * q + 0], ha.x);
            FMA2(a1, wreg[4 * q + 1], ha.y);
            FMA2(a2, wreg[4 * q + 2], hb.x);
            FMA2(a3, wreg[4 * q + 3], hb.y);
        }
        float s0, s1, s2, s3, s4, s5, s6, s7;
        asm("mov.b64 {%0,%1}, %2;" : "=f"(s0), "=f"(s1) : "l"(a0));
        asm("mov.b64 {%0,%1}, %2;" : "=f"(s2), "=f"(s3) : "l"(a1));
        asm("mov.b64 {%0,%1}, %2;" : "=f"(s4), "=f"(s5) : "l"(a2));
        asm("mov.b64 {%0,%1}, %2;" : "=f"(s6), "=f"(s7) : "l"(a3));
        float part = ((s0 + s1) + (s2 + s3)) + ((s4 + s5) + (s6 + s7));
        if (rank == 0) part += xg;

        {
            unsigned dst = rm_pbuf + (((unsigned)(t & 1) << 9) + j) * 4u;
            asm volatile(
                "st.async.shared::cluster.mbarrier::complete_tx::bytes.b32 [%0], %1, [%2];"
                :: "r"(dst), "r"(__float_as_uint(part)), "r"(rm_mbar) : "memory");
        }

        MBWAIT(mbar_a, (unsigned)(t & 1));

        float g = part + pbuf[t & 1][j];
        float act = sel_tanh ? tanh_f(g) : sig_f(g);
        a_s[j] = act;
        __syncthreads();

        if (j < 128) {
            float ai = a_s[j], af = a_s[128 + j], ag = a_s[256 + j], ao = a_s[384 + j];
            c = fmaf(af, c, ai * ag);
            h_s[j] = ao * tanh_f(c);
        }
        __syncthreads();
    }

    if (rank == 0 && j < 128) {
        out[(size_t)b * HID + j] = h_s[j];                        // h  [1,64,128]
        out[(size_t)BATCH * HID + (size_t)b * HID + j] = c;       // c  [1,64,128]
    }

    asm volatile("barrier.cluster.arrive.aligned;" ::: "memory");
    asm volatile("barrier.cluster.wait.aligned;"   ::: "memory");
}

// ---------------------------------------------------------------------------
extern "C" void kernel_launch(void* const* d_in, const int* in_sizes, int n_in,
                              void* d_out, int out_size)
{
    const int*   tokens = (const int*)  d_in[0];
    const float* emb    = (const float*)d_in[1];
    const float* W_ih   = (const float*)d_in[2];
    const float* W_hh   = (const float*)d_in[3];
    const float* b_ih   = (const float*)d_in[4];
    const float* b_hh   = (const float*)d_in[5];
    float* out = (float*)d_out;

    cudaFuncSetAttribute(proj_mma_kernel,
                         cudaFuncAttributeMaxDynamicSharedMemorySize, SM_PROJ);

    dim3 g1((VOCAB + 63) / 64, GATES / 64);   // 786 x 8
    proj_mma_kernel<<<g1, 256, SM_PROJ>>>(emb, W_ih, b_ih, b_hh);
    lstm_kernel<<<BATCH * 2, 512>>>(tokens, W_hh, out);
}

// round 10
// speedup vs baseline: 1.5382x; 1.0453x over previous
#include <cuda_runtime.h>
#include <cuda_bf16.h>
#include <math.h>

#define VOCAB 50257
#define DIM   128
#define HID   128
#define GATES 512
#define BATCH 64
#define SEQ   2048

typedef unsigned long long ull;

// Projected embedding table: P[v][g] = dot(emb[v], W_ih[g]) + b_ih[g] + b_hh[g]
__device__ float g_P[(size_t)VOCAB * GATES];
// bf16 hi/lo splits (precomputed once)
__device__ __nv_bfloat16 g_ehi[(size_t)VOCAB * DIM];
__device__ __nv_bfloat16 g_elo[(size_t)VOCAB * DIM];
__device__ __nv_bfloat16 g_whi[(size_t)GATES * DIM];
__device__ __nv_bfloat16 g_wlo[(size_t)GATES * DIM];
__device__ float g_bias[GATES];

#define FMA2(acc, a, b) \
    asm("fma.rn.f32x2 %0, %1, %2, %0;" : "+l"(acc) : "l"(a), "l"(b))

__device__ __forceinline__ unsigned cvta_smem_u32(const void* p) {
    unsigned r;
    asm("{ .reg .u64 t; cvta.to.shared.u64 t, %1; cvt.u32.u64 %0, t; }"
        : "=r"(r) : "l"(p));
    return r;
}
__device__ __forceinline__ unsigned pack_hi(float a, float b) {
    __nv_bfloat162 v = __float22bfloat162_rn(make_float2(a, b));
    return *reinterpret_cast<unsigned*>(&v);
}

// ===========================================================================
// Kernel 0: one-shot bf16 hi/lo split of emb and W_ih, + fused bias.
// ===========================================================================
#define NE4 ((VOCAB * DIM) / 4)     // 1608224 float4 groups
#define NW4 ((GATES * DIM) / 4)     // 16384

__global__ __launch_bounds__(256) void split_kernel(
    const float* __restrict__ emb,
    const float* __restrict__ W_ih,
    const float* __restrict__ b_ih,
    const float* __restrict__ b_hh)
{
    const int i = blockIdx.x * 256 + threadIdx.x;
    if (i < NE4) {
        float4 v = ((const float4*)emb)[i];
        unsigned h0 = pack_hi(v.x, v.y), h1 = pack_hi(v.z, v.w);
        __nv_bfloat162 hb0 = *reinterpret_cast<__nv_bfloat162*>(&h0);
        __nv_bfloat162 hb1 = *reinterpret_cast<__nv_bfloat162*>(&h1);
        unsigned l0 = pack_hi(v.x - __bfloat162float(hb0.x),
                              v.y - __bfloat162float(hb0.y));
        unsigned l1 = pack_hi(v.z - __bfloat162float(hb1.x),
                              v.w - __bfloat162float(hb1.y));
        ((uint2*)g_ehi)[i] = make_uint2(h0, h1);
        ((uint2*)g_elo)[i] = make_uint2(l0, l1);
    } else if (i < NE4 + NW4) {
        const int j = i - NE4;
        float4 v = ((const float4*)W_ih)[j];
        unsigned h0 = pack_hi(v.x, v.y), h1 = pack_hi(v.z, v.w);
        __nv_bfloat162 hb0 = *reinterpret_cast<__nv_bfloat162*>(&h0);
        __nv_bfloat162 hb1 = *reinterpret_cast<__nv_bfloat162*>(&h1);
        unsigned l0 = pack_hi(v.x - __bfloat162float(hb0.x),
                              v.y - __bfloat162float(hb0.y));
        unsigned l1 = pack_hi(v.z - __bfloat162float(hb1.x),
                              v.w - __bfloat162float(hb1.y));
        ((uint2*)g_whi)[j] = make_uint2(h0, h1);
        ((uint2*)g_wlo)[j] = make_uint2(l0, l1);
    } else if (i < NE4 + NW4 + GATES) {
        const int j = i - NE4 - NW4;
        g_bias[j] = b_ih[j] + b_hh[j];
    }
}

// ===========================================================================
// Kernel 1: P = emb @ W_ih^T + b via HMMA, 128x128x128 tiles, bf16 3-term.
//   256 thr / 8 warps; warp tile m32 x n64. SMEM rows padded to 136 bf16
//   (272 B) -> conflict-free ldmatrix (fragment mapping validated in R8).
// ===========================================================================
#define PROWB 272                       // bytes per padded smem row
#define T_AHI 0
#define T_ALO (T_AHI + 128 * PROWB)
#define T_BHI (T_ALO + 128 * PROWB)
#define T_BLO (T_BHI + 128 * PROWB)
#define T_BIAS (T_BLO + 128 * PROWB)
#define SM_PROJ (T_BIAS + 128 * 4)      // 139776 B

#define LDSM4(R, ADDR)                                                      \
    asm volatile("ldmatrix.sync.aligned.m8n8.x4.shared.b16 "                \
                 "{%0,%1,%2,%3}, [%4];"                                     \
                 : "=r"((R)[0]), "=r"((R)[1]), "=r"((R)[2]), "=r"((R)[3])   \
                 : "r"(ADDR))

#define MMA16816(D, A, B0, B1)                                              \
    asm volatile("mma.sync.aligned.m16n8k16.row.col.f32.bf16.bf16.f32 "     \
                 "{%0,%1,%2,%3}, {%4,%5,%6,%7}, {%8,%9}, {%0,%1,%2,%3};"    \
                 : "+f"((D)[0]), "+f"((D)[1]), "+f"((D)[2]), "+f"((D)[3])   \
                 : "r"((A)[0]), "r"((A)[1]), "r"((A)[2]), "r"((A)[3]),      \
                   "r"(B0), "r"(B1))

__global__ __launch_bounds__(256) void proj_mma_kernel(void)
{
    extern __shared__ __align__(16) unsigned char sm[];
    const unsigned base = cvta_smem_u32(sm);

    const int tid = threadIdx.x;
    const int m0  = blockIdx.x << 7;
    const int n0  = blockIdx.y << 7;

    // ---- load tiles: thread t -> row t>>1, half-row (t&1)*128 bytes ----
    // Each half-row is 64 bf16 = 128 B = EIGHT uint4 per buffer (R9 bug: was 4).
    {
        const int r    = tid >> 1;
        const int half = tid & 1;
        const int gm   = m0 + r;
        const bool av  = (gm < VOCAB);
        const uint4 z  = make_uint4(0u, 0u, 0u, 0u);

        const size_t aoff = ((size_t)(av ? gm : 0) * DIM + half * 64) * 2;
        const uint4* ah = (const uint4*)((const char*)g_ehi + aoff);
        const uint4* al = (const uint4*)((const char*)g_elo + aoff);
        const size_t boff = ((size_t)(n0 + r) * DIM + half * 64) * 2;
        const uint4* bh = (const uint4*)((const char*)g_whi + boff);
        const uint4* bl = (const uint4*)((const char*)g_wlo + boff);

        unsigned char* dA  = sm + T_AHI + r * PROWB + half * 128;
        unsigned char* dAl = sm + T_ALO + r * PROWB + half * 128;
        unsigned char* dB  = sm + T_BHI + r * PROWB + half * 128;
        unsigned char* dBl = sm + T_BLO + r * PROWB + half * 128;

        #pragma unroll
        for (int q = 0; q < 8; ++q) {
            *(uint4*)(dA  + 16 * q) = av ? ah[q] : z;
            *(uint4*)(dAl + 16 * q) = av ? al[q] : z;
            *(uint4*)(dB  + 16 * q) = bh[q];
            *(uint4*)(dBl + 16 * q) = bl[q];
        }

        if (tid < 128)
            ((float*)(sm + T_BIAS))[tid] = g_bias[n0 + tid];
    }
    __syncthreads();

    // ---- mma: warp w -> m strip (w&3)*32, n strip (w>>2)*64 ----
    const int w    = tid >> 5;
    const int lane = tid & 31;
    const int ms   = (w & 3) << 5;
    const int ns   = (w >> 2) << 6;

    float acc[2][8][4];
    #pragma unroll
    for (int mi = 0; mi < 2; ++mi)
        #pragma unroll
        for (int nt = 0; nt < 8; ++nt)
            #pragma unroll
            for (int i = 0; i < 4; ++i) acc[mi][nt][i] = 0.f;

    const int a_row = ms + (lane & 15);
    const int a_k   = (lane & 16) ? 16 : 0;
    const int b_row = ns + (lane & 7) + ((lane & 16) ? 8 : 0);
    const int b_k   = (lane & 8) ? 16 : 0;

    const unsigned A0h = base + T_AHI + a_row * PROWB + a_k;
    const unsigned A1h = A0h + 16 * PROWB;
    const unsigned A0l = base + T_ALO + a_row * PROWB + a_k;
    const unsigned A1l = A0l + 16 * PROWB;
    const unsigned Bh0 = base + T_BHI + b_row * PROWB + b_k;
    const unsigned Bl0 = base + T_BLO + b_row * PROWB + b_k;

    #pragma unroll
    for (int s = 0; s < 8; ++s) {
        const unsigned ko = s * 32;
        unsigned ah[2][4], al[2][4], bh[4][4], bl[4][4];
        LDSM4(ah[0], A0h + ko);
        LDSM4(ah[1], A1h + ko);
        LDSM4(al[0], A0l + ko);
        LDSM4(al[1], A1l + ko);
        #pragma unroll
        for (int q = 0; q < 4; ++q) {
            LDSM4(bh[q], Bh0 + q * 16 * PROWB + ko);
            LDSM4(bl[q], Bl0 + q * 16 * PROWB + ko);
        }
        #pragma unroll
        for (int mi = 0; mi < 2; ++mi) {
            #pragma unroll
            for (int q = 0; q < 4; ++q) {
                #pragma unroll
                for (int jn = 0; jn < 2; ++jn) {
                    const int nt = 2 * q + jn;
                    MMA16816(acc[mi][nt], ah[mi], bh[q][2 * jn], bh[q][2 * jn + 1]);
                    MMA16816(acc[mi][nt], ah[mi], bl[q][2 * jn], bl[q][2 * jn + 1]);
                    MMA16816(acc[mi][nt], al[mi], bh[q][2 * jn], bh[q][2 * jn + 1]);
                }
            }
        }
    }

    // ---- epilogue ----
    {
        const float* bias = (const float*)(sm + T_BIAS);
        #pragma unroll
        for (int mi = 0; mi < 2; ++mi) {
            const int row0 = m0 + ms + mi * 16 + (lane >> 2);
            const int row1 = row0 + 8;
            #pragma unroll
            for (int nt = 0; nt < 8; ++nt) {
                const int cl = ns + ((lane & 3) << 1) + nt * 8;
                const float b0 = bias[cl], b1 = bias[cl + 1];
                if (row0 < VOCAB)
                    *(float2*)(g_P + (size_t)row0 * GATES + n0 + cl) =
                        make_float2(acc[mi][nt][0] + b0, acc[mi][nt][1] + b1);
                if (row1 < VOCAB)
                    *(float2*)(g_P + (size_t)row1 * GATES + n0 + cl) =
                        make_float2(acc[mi][nt][2] + b0, acc[mi][nt][3] + b1);
            }
        }
    }
}

// ===========================================================================
// Kernel 2: recurrent LSTM — R2 version verbatim (measured 1293 us).
// ===========================================================================
__device__ __forceinline__ float sig_f(float x) {
    return __fdividef(1.f, 1.f + __expf(-x));
}
__device__ __forceinline__ float tanh_f(float x) {
    float e = __expf(fminf(-2.f * x, 30.f));
    return __fdividef(1.f - e, 1.f + e);
}
__device__ __forceinline__ unsigned cvta_smem(const void* p) {
    unsigned r;
    asm("{ .reg .u64 t; cvta.to.shared.u64 t, %1; cvt.u32.u64 %0, t; }"
        : "=r"(r) : "l"(p));
    return r;
}

#define MBWAIT(addr, par) do {                                                 \
    unsigned _done;                                                            \
    asm volatile(                                                              \
        "{\n\t.reg .pred p;\n\t"                                               \
        "mbarrier.try_wait.parity.acquire.cta.shared::cta.b64 p, [%1], %2;\n\t" \
        "selp.b32 %0, 1, 0, p;\n\t}"                                           \
        : "=r"(_done) : "r"(addr), "r"(par) : "memory");                       \
    if (!_done) {                                                              \
        asm volatile(                                                          \
            "{\n\t.reg .pred P1;\n\t"                                          \
            "WL_%=:\n\t"                                                       \
            "mbarrier.try_wait.parity.acquire.cta.shared::cta.b64 P1, [%0], %1, 0x989680;\n\t" \
            "@P1 bra.uni WD_%=;\n\t"                                           \
            "bra.uni WL_%=;\n\t"                                               \
            "WD_%=:\n\t}"                                                      \
            :: "r"(addr), "r"(par) : "memory");                                \
    }                                                                          \
} while (0)

__global__ __launch_bounds__(512, 1) __cluster_dims__(2, 1, 1)
void lstm_kernel(
    const int*   __restrict__ tokens,
    const float* __restrict__ W_hh,
    float*       __restrict__ out)
{
    __shared__ __align__(16) ull   mbar[1];
    __shared__ __align__(16) float h_s[128];
    __shared__ __align__(16) float a_s[512];
    __shared__ __align__(16) float pbuf[2][512];   // peer partials, double buffered
    __shared__ int tok_s[SEQ];

    const int j    = threadIdx.x;
    const int b    = blockIdx.x >> 1;
    const int rank = blockIdx.x & 1;
    const int peer = rank ^ 1;

    const ull* W64 = (const ull*)W_hh;

    ull wreg[32];
    #pragma unroll
    for (int kk = 0; kk < 32; ++kk)
        wreg[kk] = W64[(size_t)j * 64 + (rank << 5) + kk];

    if (rank == 0) {
        for (int idx = j; idx < SEQ; idx += 512)
            tok_s[idx] = tokens[(size_t)b * SEQ + idx];
    }
    if (j < 128) h_s[j] = 0.f;

    const unsigned mbar_a = cvta_smem(mbar);
    const unsigned pbuf_a = cvta_smem(pbuf);
    if (j == 0) {
        asm volatile("mbarrier.init.shared.b64 [%0], %1;"
                     :: "r"(mbar_a), "r"(1u) : "memory");
    }
    __syncthreads();
    asm volatile("barrier.cluster.arrive.aligned;" ::: "memory");
    asm volatile("barrier.cluster.wait.aligned;"   ::: "memory");

    unsigned rm_mbar, rm_pbuf;
    asm("mapa.shared::cluster.u32 %0, %1, %2;" : "=r"(rm_mbar) : "r"(mbar_a), "r"(peer));
    asm("mapa.shared::cluster.u32 %0, %1, %2;" : "=r"(rm_pbuf) : "r"(pbuf_a), "r"(peer));

    const float* Pp = (const float*)g_P;
    float x_cur = (rank == 0) ? __ldg(Pp + (size_t)tok_s[0] * GATES + j) : 0.f;
    float c = 0.f;
    const bool sel_tanh = ((j >> 7) == 2);   // gate order i, f, g(tanh), o
    const ulonglong2* h2 = (const ulonglong2*)(h_s + (rank << 6));

    for (int t = 0; t < SEQ; ++t) {
        if (j == 0) {
            asm volatile("mbarrier.arrive.expect_tx.shared.b64 _, [%0], %1;"
                         :: "r"(mbar_a), "r"(2048u) : "memory");
        }

        float xg = x_cur;
        if (rank == 0 && t + 1 < SEQ)
            x_cur = __ldg(Pp + (size_t)tok_s[t + 1] * GATES + j);

        ull a0 = 0ull, a1 = 0ull, a2 = 0ull, a3 = 0ull;
        #pragma unroll
        for (int q = 0; q < 8; ++q) {
            ulonglong2 ha = h2[2 * q];
            ulonglong2 hb = h2[2 * q + 1];
            FMA2(a0, wreg[4 * q + 0], ha.x);
            FMA2(a1, wreg[4 * q + 1], ha.y);
            FMA2(a2, wreg[4 * q + 2], hb.x);
            FMA2(a3, wreg[4 * q + 3], hb.y);
        }
        float s0, s1, s2, s3, s4, s5, s6, s7;
        asm("mov.b64 {%0,%1}, %2;" : "=f"(s0), "=f"(s1) : "l"(a0));
        asm("mov.b64 {%0,%1}, %2;" : "=f"(s2), "=f"(s3) : "l"(a1));
        asm("mov.b64 {%0,%1}, %2;" : "=f"(s4), "=f"(s5) : "l"(a2));
        asm("mov.b64 {%0,%1}, %2;" : "=f"(s6), "=f"(s7) : "l"(a3));
        float part = ((s0 + s1) + (s2 + s3)) + ((s4 + s5) + (s6 + s7));
        if (rank == 0) part += xg;

        {
            unsigned dst = rm_pbuf + (((unsigned)(t & 1) << 9) + j) * 4u;
            asm volatile(
                "st.async.shared::cluster.mbarrier::complete_tx::bytes.b32 [%0], %1, [%2];"
                :: "r"(dst), "r"(__float_as_uint(part)), "r"(rm_mbar) : "memory");
        }

        MBWAIT(mbar_a, (unsigned)(t & 1));

        float g = part + pbuf[t & 1][j];
        float act = sel_tanh ? tanh_f(g) : sig_f(g);
        a_s[j] = act;
        __syncthreads();

        if (j < 128) {
            float ai = a_s[j], af = a_s[128 + j], ag = a_s[256 + j], ao = a_s[384 + j];
            c = fmaf(af, c, ai * ag);
            h_s[j] = ao * tanh_f(c);
        }
        __syncthreads();
    }

    if (rank == 0 && j < 128) {
        out[(size_t)b * HID + j] = h_s[j];                        // h  [1,64,128]
        out[(size_t)BATCH * HID + (size_t)b * HID + j] = c;       // c  [1,64,128]
    }

    asm volatile("barrier.cluster.arrive.aligned;" ::: "memory");
    asm volatile("barrier.cluster.wait.aligned;"   ::: "memory");
}

// ---------------------------------------------------------------------------
extern "C" void kernel_launch(void* const* d_in, const int* in_sizes, int n_in,
                              void* d_out, int out_size)
{
    const int*   tokens = (const int*)  d_in[0];
    const float* emb    = (const float*)d_in[1];
    const float* W_ih   = (const float*)d_in[2];
    const float* W_hh   = (const float*)d_in[3];
    const float* b_ih   = (const float*)d_in[4];
    const float* b_hh   = (const float*)d_in[5];
    float* out = (float*)d_out;

    cudaFuncSetAttribute(proj_mma_kernel,
                         cudaFuncAttributeMaxDynamicSharedMemorySize, SM_PROJ);

    const int ntot = NE4 + NW4 + GATES;
    split_kernel<<<(ntot + 255) / 256, 256>>>(emb, W_ih, b_ih, b_hh);

    dim3 g1((VOCAB + 127) / 128, GATES / 128);   // 393 x 4
    proj_mma_kernel<<<g1, 256, SM_PROJ>>>();

    lstm_kernel<<<BATCH * 2, 512>>>(tokens, W_hh, out);
}